// round 3
// baseline (speedup 1.0000x reference)
#include <cuda_runtime.h>
#include <math.h>

#define NN 100000
#define EE 600000
#define CC 128
#define FIN 64
#define OO 8
#define NEG 0.2f

// ---------------- scratch ----------------
__device__ float g_h[NN * CC];
__device__ float g_att[NN * 8];
__device__ float g_out0[NN * CC];
__device__ float g_out1[NN * CC];
__device__ int   g_cnt[2 * NN];
__device__ int   g_rowptr[2 * (NN + 1)];
__device__ int   g_off[2 * NN];
__device__ int   g_esrc[2 * EE];
__device__ float g_scores[4];

// ---------------- helpers ----------------
__device__ __forceinline__ float warp_sum(float v) {
#pragma unroll
    for (int o = 16; o > 0; o >>= 1) v += __shfl_xor_sync(0xffffffffu, v, o);
    return v;
}
__device__ __forceinline__ float warp_max(float v) {
#pragma unroll
    for (int o = 16; o > 0; o >>= 1) v = fmaxf(v, __shfl_xor_sync(0xffffffffu, v, o));
    return v;
}
__device__ __forceinline__ float leaky(float x) { return x > 0.f ? x : NEG * x; }

__device__ __forceinline__ unsigned f2tf(float x) {
    unsigned r;
    asm("cvt.rna.tf32.f32 %0, %1;" : "=r"(r) : "f"(x));
    return r;
}
__device__ __forceinline__ void split_tf(float v, unsigned& hi, unsigned& lo) {
    unsigned h = f2tf(v);
    hi = h;
    lo = f2tf(v - __uint_as_float(h));
}
// pack two floats to bf16x2: lo -> low half, hi -> high half
__device__ __forceinline__ unsigned packbf(float lo, float hi) {
    unsigned r;
    asm("cvt.rn.bf16x2.f32 %0, %1, %2;" : "=r"(r) : "f"(hi), "f"(lo));
    return r;
}
__device__ __forceinline__ void mma8(float* c, const unsigned* a, const unsigned* b) {
    asm volatile(
        "mma.sync.aligned.m16n8k8.row.col.f32.tf32.tf32.f32 "
        "{%0,%1,%2,%3},{%4,%5,%6,%7},{%8,%9},{%0,%1,%2,%3};\n"
        : "+f"(c[0]), "+f"(c[1]), "+f"(c[2]), "+f"(c[3])
        : "r"(a[0]), "r"(a[1]), "r"(a[2]), "r"(a[3]), "r"(b[0]), "r"(b[1]));
}
__device__ __forceinline__ void mma16bf(float* c, const unsigned* a, const unsigned* b) {
    asm volatile(
        "mma.sync.aligned.m16n8k16.row.col.f32.bf16.bf16.f32 "
        "{%0,%1,%2,%3},{%4,%5,%6,%7},{%8,%9},{%0,%1,%2,%3};\n"
        : "+f"(c[0]), "+f"(c[1]), "+f"(c[2]), "+f"(c[3])
        : "r"(a[0]), "r"(a[1]), "r"(a[2]), "r"(a[3]), "r"(b[0]), "r"(b[1]));
}

// ---------------- CSR build ----------------
__global__ void zero_kernel() {
    int i = blockIdx.x * blockDim.x + threadIdx.x;
    if (i < 2 * NN) g_cnt[i] = 0;
    if (i < 4) g_scores[i] = 0.f;
}

__global__ void hist_kernel(const int* __restrict__ ei0, const int* __restrict__ ei1) {
    int i = blockIdx.x * blockDim.x + threadIdx.x;
    if (i >= 2 * EE) return;
    int t = i / EE, e = i - t * EE;
    const int* ei = t ? ei1 : ei0;
    atomicAdd(&g_cnt[t * NN + ei[EE + e]], 1);
}

__global__ void scan_kernel() {
    const int t = blockIdx.x;
    const int tid = threadIdx.x;
    const int CH = (NN + 1023) / 1024;
    int start = tid * CH;
    int end = min(start + CH, NN);
    int s = 0;
    for (int i = start; i < end; i++) s += g_cnt[t * NN + i];
    __shared__ int sums[1024];
    sums[tid] = s;
    __syncthreads();
    for (int off = 1; off < 1024; off <<= 1) {
        int v = (tid >= off) ? sums[tid - off] : 0;
        __syncthreads();
        sums[tid] += v;
        __syncthreads();
    }
    int run = sums[tid] - s;
    for (int i = start; i < end; i++) {
        g_rowptr[t * (NN + 1) + i] = run;
        g_off[t * NN + i] = run;
        run += g_cnt[t * NN + i];
    }
    if (tid == 1023) g_rowptr[t * (NN + 1) + NN] = sums[1023];
}

__global__ void scatter_kernel(const int* __restrict__ ei0, const int* __restrict__ ei1) {
    int i = blockIdx.x * blockDim.x + threadIdx.x;
    if (i >= 2 * EE) return;
    int t = i / EE, e = i - t * EE;
    const int* ei = t ? ei1 : ei0;
    int dst = ei[EE + e];
    int pos = atomicAdd(&g_off[t * NN + dst], 1);
    g_esrc[t * EE + pos] = ei[e];
}

// ---------------- unified tensor-core GEMM ----------------
// MODE 0: g_h = A@W + bias (bk=bias). COMB=1: A = relu(softmax(scores)-combined outs).
//         PRECISE=1 -> 3xTF32 near-fp32 path.
// MODE 1: semantic score: atomicAdd(sum_n q . tanh(row + kb)); A = g_out{blockIdx.y}.
//         B16=1 -> bf16 mma (k16).
template <int K, int MODE, int PRECISE, int B16, int COMB>
__global__ __launch_bounds__(256) void mm_kernel(const float* __restrict__ Ain,
                                                 const float* __restrict__ W,
                                                 const float* __restrict__ bk,
                                                 const float* __restrict__ q,
                                                 int sidx) {
    const float* A;
    if (MODE == 1) A = blockIdx.y ? g_out1 : g_out0;
    else A = Ain;

    float ca = 0.f, cbw = 0.f;
    if (COMB) {
        float s0 = g_scores[sidx] * (1.f / NN);
        float s1 = g_scores[sidx + 1] * (1.f / NN);
        float mx = fmaxf(s0, s1);
        float e0 = expf(s0 - mx), e1 = expf(s1 - mx);
        ca = e0 / (e0 + e1);
        cbw = 1.f - ca;
    }

    __shared__ float As[2][128][20];
    __shared__ float Bs[2][16][136];
    __shared__ float red[8];

    const int tid = threadIdx.x;
    const int row0 = blockIdx.x * 128;
    const int lane = tid & 31, wid = tid >> 5;
    const int wm = wid & 3, wn = wid >> 2;
    const int gid = lane >> 2, tig = lane & 3;
    const int NKC = K / 16;

    float acc[2][8][4];
#pragma unroll
    for (int mt = 0; mt < 2; mt++)
#pragma unroll
        for (int nt = 0; nt < 8; nt++)
#pragma unroll
            for (int e = 0; e < 4; e++) acc[mt][nt][e] = 0.f;

    const int ar = tid >> 2;
    const int ak = (tid & 3) * 4;
    const int bkr = tid >> 5;
    const int bc = (tid & 31) * 4;

    float4 pa[2], pb[2];
#pragma unroll
    for (int i = 0; i < 2; i++) {
        int r = row0 + ar + 64 * i;
        if (r < NN) {
            if (COMB) {
                float4 u = *reinterpret_cast<const float4*>(g_out0 + (size_t)r * K + ak);
                float4 v = *reinterpret_cast<const float4*>(g_out1 + (size_t)r * K + ak);
                pa[i].x = fmaxf(ca * u.x + cbw * v.x, 0.f);
                pa[i].y = fmaxf(ca * u.y + cbw * v.y, 0.f);
                pa[i].z = fmaxf(ca * u.z + cbw * v.z, 0.f);
                pa[i].w = fmaxf(ca * u.w + cbw * v.w, 0.f);
            } else
                pa[i] = *reinterpret_cast<const float4*>(A + (size_t)r * K + ak);
        } else
            pa[i] = make_float4(0.f, 0.f, 0.f, 0.f);
        pb[i] = *reinterpret_cast<const float4*>(W + (size_t)(bkr + 8 * i) * CC + bc);
    }
#pragma unroll
    for (int i = 0; i < 2; i++) {
        *reinterpret_cast<float4*>(&As[0][ar + 64 * i][ak]) = pa[i];
        *reinterpret_cast<float4*>(&Bs[0][bkr + 8 * i][bc]) = pb[i];
    }
    __syncthreads();

    int buf = 0;
    for (int ch = 0; ch < NKC; ch++) {
        if (ch + 1 < NKC) {
            int k0 = (ch + 1) * 16;
#pragma unroll
            for (int i = 0; i < 2; i++) {
                int r = row0 + ar + 64 * i;
                if (r < NN) {
                    if (COMB) {
                        float4 u = *reinterpret_cast<const float4*>(g_out0 + (size_t)r * K + k0 + ak);
                        float4 v = *reinterpret_cast<const float4*>(g_out1 + (size_t)r * K + k0 + ak);
                        pa[i].x = fmaxf(ca * u.x + cbw * v.x, 0.f);
                        pa[i].y = fmaxf(ca * u.y + cbw * v.y, 0.f);
                        pa[i].z = fmaxf(ca * u.z + cbw * v.z, 0.f);
                        pa[i].w = fmaxf(ca * u.w + cbw * v.w, 0.f);
                    } else
                        pa[i] = *reinterpret_cast<const float4*>(A + (size_t)r * K + k0 + ak);
                } else
                    pa[i] = make_float4(0.f, 0.f, 0.f, 0.f);
                pb[i] = *reinterpret_cast<const float4*>(W + (size_t)(k0 + bkr + 8 * i) * CC + bc);
            }
        }
        if (B16) {
            // bf16 mma, one k16 step
            unsigned af[2][4];
#pragma unroll
            for (int mt = 0; mt < 2; mt++) {
                int rb = wm * 32 + mt * 16 + gid;
                float2 f0 = *reinterpret_cast<const float2*>(&As[buf][rb][2 * tig]);
                float2 f1 = *reinterpret_cast<const float2*>(&As[buf][rb + 8][2 * tig]);
                float2 f2 = *reinterpret_cast<const float2*>(&As[buf][rb][2 * tig + 8]);
                float2 f3 = *reinterpret_cast<const float2*>(&As[buf][rb + 8][2 * tig + 8]);
                af[mt][0] = packbf(f0.x, f0.y);
                af[mt][1] = packbf(f1.x, f1.y);
                af[mt][2] = packbf(f2.x, f2.y);
                af[mt][3] = packbf(f3.x, f3.y);
            }
#pragma unroll
            for (int nt = 0; nt < 8; nt++) {
                int cb = wn * 64 + nt * 8 + gid;
                unsigned bf[2];
                bf[0] = packbf(Bs[buf][2 * tig][cb], Bs[buf][2 * tig + 1][cb]);
                bf[1] = packbf(Bs[buf][2 * tig + 8][cb], Bs[buf][2 * tig + 9][cb]);
#pragma unroll
                for (int mt = 0; mt < 2; mt++) mma16bf(acc[mt][nt], af[mt], bf);
            }
        } else {
#pragma unroll
            for (int ks = 0; ks < 16; ks += 8) {
                if (PRECISE) {
                    unsigned ahi[2][4], alo[2][4];
#pragma unroll
                    for (int mt = 0; mt < 2; mt++) {
                        int rb = wm * 32 + mt * 16 + gid;
                        split_tf(As[buf][rb][ks + tig], ahi[mt][0], alo[mt][0]);
                        split_tf(As[buf][rb + 8][ks + tig], ahi[mt][1], alo[mt][1]);
                        split_tf(As[buf][rb][ks + tig + 4], ahi[mt][2], alo[mt][2]);
                        split_tf(As[buf][rb + 8][ks + tig + 4], ahi[mt][3], alo[mt][3]);
                    }
#pragma unroll
                    for (int nt = 0; nt < 8; nt++) {
                        int cb = wn * 64 + nt * 8 + gid;
                        unsigned bhi[2], blo[2];
                        split_tf(Bs[buf][ks + tig][cb], bhi[0], blo[0]);
                        split_tf(Bs[buf][ks + tig + 4][cb], bhi[1], blo[1]);
#pragma unroll
                        for (int mt = 0; mt < 2; mt++) {
                            mma8(acc[mt][nt], ahi[mt], blo);
                            mma8(acc[mt][nt], alo[mt], bhi);
                            mma8(acc[mt][nt], ahi[mt], bhi);
                        }
                    }
                } else {
                    unsigned af[2][4];
#pragma unroll
                    for (int mt = 0; mt < 2; mt++) {
                        int rb = wm * 32 + mt * 16 + gid;
                        af[mt][0] = f2tf(As[buf][rb][ks + tig]);
                        af[mt][1] = f2tf(As[buf][rb + 8][ks + tig]);
                        af[mt][2] = f2tf(As[buf][rb][ks + tig + 4]);
                        af[mt][3] = f2tf(As[buf][rb + 8][ks + tig + 4]);
                    }
#pragma unroll
                    for (int nt = 0; nt < 8; nt++) {
                        int cb = wn * 64 + nt * 8 + gid;
                        unsigned bf[2];
                        bf[0] = f2tf(Bs[buf][ks + tig][cb]);
                        bf[1] = f2tf(Bs[buf][ks + tig + 4][cb]);
#pragma unroll
                        for (int mt = 0; mt < 2; mt++) mma8(acc[mt][nt], af[mt], bf);
                    }
                }
            }
        }
        if (ch + 1 < NKC) {
#pragma unroll
            for (int i = 0; i < 2; i++) {
                *reinterpret_cast<float4*>(&As[buf ^ 1][ar + 64 * i][ak]) = pa[i];
                *reinterpret_cast<float4*>(&Bs[buf ^ 1][bkr + 8 * i][bc]) = pb[i];
            }
            __syncthreads();
            buf ^= 1;
        }
    }

    if (MODE == 0) {
#pragma unroll
        for (int nt = 0; nt < 8; nt++) {
            int c = wn * 64 + nt * 8 + 2 * tig;
            float b0 = bk[c], b1 = bk[c + 1];
#pragma unroll
            for (int mt = 0; mt < 2; mt++) {
                int r = row0 + wm * 32 + mt * 16 + gid;
                if (r < NN) {
                    float2 o = {acc[mt][nt][0] + b0, acc[mt][nt][1] + b1};
                    *reinterpret_cast<float2*>(g_h + (size_t)r * CC + c) = o;
                }
                if (r + 8 < NN) {
                    float2 o = {acc[mt][nt][2] + b0, acc[mt][nt][3] + b1};
                    *reinterpret_cast<float2*>(g_h + (size_t)(r + 8) * CC + c) = o;
                }
            }
        }
    } else {
        float local = 0.f;
#pragma unroll
        for (int nt = 0; nt < 8; nt++) {
            int c = wn * 64 + nt * 8 + 2 * tig;
            float q0 = q[c], q1 = q[c + 1];
            float k0v = bk[c], k1v = bk[c + 1];
#pragma unroll
            for (int mt = 0; mt < 2; mt++) {
                int r = row0 + wm * 32 + mt * 16 + gid;
                if (r < NN)
                    local += q0 * tanhf(acc[mt][nt][0] + k0v) + q1 * tanhf(acc[mt][nt][1] + k1v);
                if (r + 8 < NN)
                    local += q0 * tanhf(acc[mt][nt][2] + k0v) + q1 * tanhf(acc[mt][nt][3] + k1v);
            }
        }
        local = warp_sum(local);
        if (lane == 0) red[wid] = local;
        __syncthreads();
        if (tid == 0) {
            float t = 0.f;
#pragma unroll
            for (int k = 0; k < 8; k++) t += red[k];
            atomicAdd(&g_scores[sidx + blockIdx.y], t);
        }
    }
}

// ---------------- per-node attention dot products ----------------
__global__ void att_kernel(const float* __restrict__ as_, const float* __restrict__ ad_) {
    int wid = threadIdx.x >> 5, lane = threadIdx.x & 31;
    int n = blockIdx.x * 8 + wid;
    if (n >= NN) return;
    const float* hr = g_h + (size_t)n * CC;
    float v0 = hr[lane], v1 = hr[32 + lane], v2 = hr[64 + lane], v3 = hr[96 + lane];
    float r[8];
    r[0] = v0 * as_[lane] + v1 * as_[32 + lane];
    r[1] = v2 * as_[64 + lane] + v3 * as_[96 + lane];
    r[2] = v0 * as_[128 + lane] + v1 * as_[160 + lane];
    r[3] = v2 * as_[192 + lane] + v3 * as_[224 + lane];
    r[4] = v0 * ad_[lane] + v1 * ad_[32 + lane];
    r[5] = v2 * ad_[64 + lane] + v3 * ad_[96 + lane];
    r[6] = v0 * ad_[128 + lane] + v1 * ad_[160 + lane];
    r[7] = v2 * ad_[192 + lane] + v3 * ad_[224 + lane];
#pragma unroll
    for (int k = 0; k < 8; k++) r[k] = warp_sum(r[k]);
    if (lane == 0) {
#pragma unroll
        for (int k = 0; k < 8; k++) g_att[n * 8 + k] = r[k];
    }
}

// ---------------- edge softmax + aggregation ----------------
// warp per dst node; blockIdx.y = edge type. Lane-parallel alpha/exp phase,
// shuffle-broadcast accumulation phase (coalesced 512B row gathers only).
__global__ void agg_kernel() {
    const int t = blockIdx.y;
    int wid = threadIdx.x >> 5, lane = threadIdx.x & 31;
    int n = blockIdx.x * 8 + wid;
    if (n >= NN) return;
    float* outp = t ? g_out1 : g_out0;
    const int base = g_rowptr[t * (NN + 1) + n];
    const int deg = g_rowptr[t * (NN + 1) + n + 1] - base;
    const float ad0 = g_att[n * 8 + 4 + 2 * t];
    const float ad1 = g_att[n * 8 + 5 + 2 * t];
    const int* ep = g_esrc + t * EE + base;

    // phase 1: alpha + max (chunk 0 kept in registers)
    float m0 = -3.0e38f, m1 = -3.0e38f;
    int src0_ = 0;
    float a0_ = -3.0e38f, a1_ = -3.0e38f;
    for (int j0 = 0; j0 < deg; j0 += 32) {
        int j = j0 + lane;
        int src = 0;
        float a0 = -3.0e38f, a1 = -3.0e38f;
        if (j < deg) {
            src = ep[j];
            float2 s = *reinterpret_cast<const float2*>(g_att + (size_t)src * 8 + 2 * t);
            a0 = leaky(s.x + ad0);
            a1 = leaky(s.y + ad1);
        }
        if (j0 == 0) { src0_ = src; a0_ = a0; a1_ = a1; }
        m0 = fmaxf(m0, a0);
        m1 = fmaxf(m1, a1);
    }
    m0 = warp_max(m0);
    m1 = warp_max(m1);

    // phase 2: exp weights (lane-parallel) + broadcast accumulation
    float sum0 = 0.f, sum1 = 0.f;
    float acc0 = 0.f, acc1 = 0.f, acc2 = 0.f, acc3 = 0.f;
    for (int j0 = 0; j0 < deg; j0 += 32) {
        int j = j0 + lane;
        int src;
        float w0, w1;
        if (j0 == 0) {
            src = src0_;
            w0 = (j < deg) ? expf(a0_ - m0) : 0.f;
            w1 = (j < deg) ? expf(a1_ - m1) : 0.f;
        } else {
            src = 0; w0 = 0.f; w1 = 0.f;
            if (j < deg) {
                src = ep[j];
                float2 s = *reinterpret_cast<const float2*>(g_att + (size_t)src * 8 + 2 * t);
                w0 = expf(leaky(s.x + ad0) - m0);
                w1 = expf(leaky(s.y + ad1) - m1);
            }
        }
        sum0 += w0;
        sum1 += w1;
        int cnt = min(32, deg - j0);
#pragma unroll 4
        for (int i = 0; i < cnt; i++) {
            float u0 = __shfl_sync(0xffffffffu, w0, i);
            float u1 = __shfl_sync(0xffffffffu, w1, i);
            int s = __shfl_sync(0xffffffffu, src, i);
            const float* hr = g_h + (size_t)s * CC;
            acc0 += u0 * hr[lane];
            acc1 += u0 * hr[32 + lane];
            acc2 += u1 * hr[64 + lane];
            acc3 += u1 * hr[96 + lane];
        }
    }
    sum0 = warp_sum(sum0);
    sum1 = warp_sum(sum1);
    float r0 = 1.f / (sum0 + 1e-16f);
    float r1 = 1.f / (sum1 + 1e-16f);
    float* orow = outp + (size_t)n * CC;
    orow[lane] = fmaxf(acc0 * r0, 0.f);
    orow[32 + lane] = fmaxf(acc1 * r0, 0.f);
    orow[64 + lane] = fmaxf(acc2 * r1, 0.f);
    orow[96 + lane] = fmaxf(acc3 * r1, 0.f);
}

// ---------------- final linear (fused semantic combine) ----------------
__global__ void final_kernel(const float* __restrict__ lw, const float* __restrict__ lb,
                             float* __restrict__ out) {
    int i = blockIdx.x * blockDim.x + threadIdx.x;
    if (i >= NN * OO) return;
    int n = i >> 3, o = i & 7;
    float s0 = g_scores[2] * (1.f / NN);
    float s1 = g_scores[3] * (1.f / NN);
    float mx = fmaxf(s0, s1);
    float e0 = expf(s0 - mx), e1 = expf(s1 - mx);
    float ca = e0 / (e0 + e1);
    float cbw = 1.f - ca;
    float acc = lb[o];
    const float* r0p = g_out0 + (size_t)n * CC;
    const float* r1p = g_out1 + (size_t)n * CC;
#pragma unroll 8
    for (int c = 0; c < CC; c++) {
        float v = fmaxf(ca * r0p[c] + cbw * r1p[c], 0.f);
        acc += v * lw[c * OO + o];
    }
    out[i] = acc;
}

// ---------------- launch ----------------
extern "C" void kernel_launch(void* const* d_in, const int* in_sizes, int n_in,
                              void* d_out, int out_size) {
    const float *x = 0, *p1w = 0, *p1b = 0, *p1as = 0, *p1ad = 0, *p1q = 0, *p1kw = 0, *p1kb = 0;
    const float *p2w = 0, *p2b = 0, *p2as = 0, *p2ad = 0, *p2q = 0, *p2kw = 0, *p2kb = 0;
    const float *linw = 0, *linb = 0;
    const int *ei0 = 0, *ei1 = 0;
    int nEi = 0, n16k = 0, n256 = 0, n128 = 0;
    for (int i = 0; i < n_in; i++) {
        const float* fp = (const float*)d_in[i];
        switch (in_sizes[i]) {
            case NN * FIN: x = fp; break;
            case 2 * EE:
                if (nEi == 0) ei0 = (const int*)d_in[i];
                else ei1 = (const int*)d_in[i];
                nEi++;
                break;
            case FIN * CC: p1w = fp; break;
            case CC * CC:
                if (n16k == 0) p1kw = fp;
                else if (n16k == 1) p2w = fp;
                else p2kw = fp;
                n16k++;
                break;
            case 256:
                if (n256 == 0) p1as = fp;
                else if (n256 == 1) p1ad = fp;
                else if (n256 == 2) p2as = fp;
                else p2ad = fp;
                n256++;
                break;
            case CC:
                if (n128 == 0) p1b = fp;
                else if (n128 == 1) p1q = fp;
                else if (n128 == 2) p1kb = fp;
                else if (n128 == 3) p2b = fp;
                else if (n128 == 4) p2q = fp;
                else p2kb = fp;
                n128++;
                break;
            case CC * OO: linw = fp; break;
            case OO: linb = fp; break;
            default: break;
        }
    }

    const int GRID_MM = (NN + 127) / 128;       // 782
    const int GRID_NODE = (NN + 7) / 8;         // 12500
    const int GRID_EDGE = (2 * EE + 255) / 256; // 4688

    zero_kernel<<<(2 * NN + 255) / 256, 256>>>();
    hist_kernel<<<GRID_EDGE, 256>>>(ei0, ei1);
    scan_kernel<<<2, 1024>>>();
    scatter_kernel<<<GRID_EDGE, 256>>>(ei0, ei1);

    // ---- layer 1 ----
    mm_kernel<FIN, 0, 1, 0, 0><<<GRID_MM, 256>>>(x, p1w, p1b, nullptr, 0);
    att_kernel<<<GRID_NODE, 256>>>(p1as, p1ad);
    agg_kernel<<<dim3(GRID_NODE, 2), 256>>>();
    mm_kernel<CC, 1, 0, 1, 0><<<dim3(GRID_MM, 2), 256>>>(nullptr, p1kw, p1kb, p1q, 0);

    // ---- layer 2 (combine fused into proj A-load) ----
    mm_kernel<CC, 0, 1, 0, 1><<<GRID_MM, 256>>>(nullptr, p2w, p2b, nullptr, 0);
    att_kernel<<<GRID_NODE, 256>>>(p2as, p2ad);
    agg_kernel<<<dim3(GRID_NODE, 2), 256>>>();
    mm_kernel<CC, 1, 0, 1, 0><<<dim3(GRID_MM, 2), 256>>>(nullptr, p2kw, p2kb, p2q, 2);

    // ---- classifier (combine fused) ----
    final_kernel<<<(NN * OO + 255) / 256, 256>>>(linw, linb, (float*)d_out);
}